// round 12
// baseline (speedup 1.0000x reference)
#include <cuda_runtime.h>
#include <cuda_bf16.h>
#include <cstdint>

// ---------------------------------------------------------------------------
// Problem constants
// ---------------------------------------------------------------------------
#define BATCH   128
#define T_STEPS 256
#define IN_F    1024
#define OUT_C   512
#define M_TOTAL (BATCH * T_STEPS)   // 32768
#define NKT     32                  // IN_F / 32 k-chunks

// SNN hyperparameters
#define V_TH      0.4f
#define LEAK      0.01f
#define REFR_LEAK 0.01f
#define REFRAC    2.0f

// ---------------------------------------------------------------------------
// Device scratch (static __device__: allocation-guard safe)
// ---------------------------------------------------------------------------
__device__ __align__(128) unsigned char g_Ah[(size_t)M_TOTAL * IN_F * 2]; // 64MB
__device__ __align__(128) unsigned char g_Al[(size_t)M_TOTAL * IN_F * 2]; // 64MB
__device__ __align__(128) unsigned char g_Bh[(size_t)OUT_C * IN_F * 2];   // 1MB
__device__ __align__(128) unsigned char g_Bl[(size_t)OUT_C * IN_F * 2];   // 1MB
__device__ float g_I[(size_t)M_TOTAL * OUT_C];                            // 64MB

// Cross-CTA dataflow flags (zero-init; protocols restore 0 every run).
__device__ int g_aDone[256];     // eighths converted per m-tile (0..8)
__device__ int g_aPassed[256];   // consumers past the spin     (0..8)
__device__ int g_pDone[128 * 8]; // I-tiles written per (b, nt) pair (0..2)

// ---------------------------------------------------------------------------
// Helpers (base sm_80/90 ISA only — nothing 'a'-gated)
// ---------------------------------------------------------------------------
__device__ __forceinline__ uint32_t smem_u32(const void* p) {
    uint32_t a;
    asm("{ .reg .u64 t; cvta.to.shared.u64 t, %1; cvt.u32.u64 %0, t; }"
        : "=r"(a) : "l"(p));
    return a;
}

__device__ __forceinline__ void cp_async16(uint32_t dst, const void* src) {
    asm volatile("cp.async.cg.shared.global [%0], [%1], 16;"
                 :: "r"(dst), "l"(src) : "memory");
}
#define CP_COMMIT() asm volatile("cp.async.commit_group;" ::: "memory")
#define CP_WAIT1()  asm volatile("cp.async.wait_group 1;" ::: "memory")

__device__ __forceinline__ void ldmatrix_x4(uint32_t* r, uint32_t addr) {
    asm volatile("ldmatrix.sync.aligned.m8n8.x4.shared.b16 {%0,%1,%2,%3}, [%4];"
                 : "=r"(r[0]), "=r"(r[1]), "=r"(r[2]), "=r"(r[3]) : "r"(addr));
}

__device__ __forceinline__ void mma16816(float* d, const uint32_t* a,
                                         uint32_t b0, uint32_t b1) {
    asm volatile(
        "mma.sync.aligned.m16n8k16.row.col.f32.bf16.bf16.f32 "
        "{%0,%1,%2,%3}, {%4,%5,%6,%7}, {%8,%9}, {%0,%1,%2,%3};"
        : "+f"(d[0]), "+f"(d[1]), "+f"(d[2]), "+f"(d[3])
        : "r"(a[0]), "r"(a[1]), "r"(a[2]), "r"(a[3]), "r"(b0), "r"(b1));
}

__device__ __forceinline__ int ld_acquire(const int* p) {
    int v;
    asm volatile("ld.acquire.gpu.s32 %0, [%1];" : "=r"(v) : "l"(p) : "memory");
    return v;
}

// Swizzled byte offset within an (up to 128)-row x 64-byte tile
// (conflict-free ldmatrix). 2 rows per 128B line.
__device__ __forceinline__ uint32_t tile_off(int r, int c) {
    int line = r >> 1;
    int ch8 = (((r & 1) * 4 + c) ^ (line & 7));
    return (uint32_t)(line * 128 + ch8 * 16);
}

// fp32 -> (hi, lo) bf16 pair packers
__device__ __forceinline__ void split4(float4 v, uint2& ph, uint2& pl) {
    __nv_bfloat16 h0 = __float2bfloat16_rn(v.x);
    __nv_bfloat16 h1 = __float2bfloat16_rn(v.y);
    __nv_bfloat16 h2 = __float2bfloat16_rn(v.z);
    __nv_bfloat16 h3 = __float2bfloat16_rn(v.w);
    __nv_bfloat16 l0 = __float2bfloat16_rn(v.x - __bfloat162float(h0));
    __nv_bfloat16 l1 = __float2bfloat16_rn(v.y - __bfloat162float(h1));
    __nv_bfloat16 l2 = __float2bfloat16_rn(v.z - __bfloat162float(h2));
    __nv_bfloat16 l3 = __float2bfloat16_rn(v.w - __bfloat162float(h3));
    ph.x = ((uint32_t)__bfloat16_as_ushort(h1) << 16) | __bfloat16_as_ushort(h0);
    ph.y = ((uint32_t)__bfloat16_as_ushort(h3) << 16) | __bfloat16_as_ushort(h2);
    pl.x = ((uint32_t)__bfloat16_as_ushort(l1) << 16) | __bfloat16_as_ushort(l0);
    pl.y = ((uint32_t)__bfloat16_as_ushort(l3) << 16) | __bfloat16_as_ushort(l2);
}

// ---------------------------------------------------------------------------
// conv_B: W fp32 [1024 k][512 n] -> g_Bh / g_Bl bf16 [n][1024 k]
// ---------------------------------------------------------------------------
__global__ __launch_bounds__(256)
void conv_B_kernel(const float* __restrict__ W) {
    const uint32_t i = blockIdx.x * 256 + threadIdx.x;   // 0 .. 524287
    const uint32_t k = i & 1023;
    const uint32_t n = i >> 10;
    float w = W[(size_t)k * OUT_C + n];
    __nv_bfloat16 hi = __float2bfloat16_rn(w);
    __nv_bfloat16 lo = __float2bfloat16_rn(w - __bfloat162float(hi));
    *(unsigned short*)(g_Bh + ((size_t)n * IN_F + k) * 2) = __bfloat16_as_ushort(hi);
    *(unsigned short*)(g_Bl + ((size_t)n * IN_F + k) * 2) = __bfloat16_as_ushort(lo);
}

// ---------------------------------------------------------------------------
// Fused kernel: A-convert (eighth per CTA) -> GEMM -> I-tile -> pairwise scan.
// CTA tile 128x64, BK=32, 8 warps (4x2, warp tile 32x32), mma.sync 16x8x16.
// 3-stage cp.async pipeline; stage = Ah(8K)|Al(8K)|Bh(4K)|Bl(4K) = 24KB.
// __launch_bounds__(256,3): 3 CTAs/SM (24 warps) for latency hiding.
// ---------------------------------------------------------------------------
#define STG_SZ  24576
#define GEMM_SMEM (3 * STG_SZ)   // 72KB -> 3 CTAs/SM

__global__ __launch_bounds__(256, 3)
void snn_fused(const float* __restrict__ x, float* __restrict__ out) {
    extern __shared__ __align__(1024) unsigned char dsm[];
    const uint32_t sb = smem_u32(dsm);

    const int tid  = threadIdx.x;
    const int lane = tid & 31;
    const int wid  = tid >> 5;
    const int wm   = wid >> 1;          // 0..3
    const int wn   = wid & 1;           // 0..1
    const int nt   = blockIdx.x;        // 0..7
    const int yb   = blockIdx.y;        // 0..255
    const int mBase = yb * 128;
    const int nBase = nt * 64;

    // ======== Phase 1: convert this CTA's eighth (16 rows) of A ========
    {
        const int qBase = mBase + nt * 16;
        const float4* src = (const float4*)x + (size_t)qBase * 256;
        #pragma unroll 4
        for (int it = 0; it < 16; it++) {
            const int idx = it * 256 + tid;          // 0..4095
            const int r   = idx >> 8;                // 0..15
            const int c4  = idx & 255;
            uint2 ph, pl;
            split4(src[(size_t)r * 256 + c4], ph, pl);
            const size_t base = ((size_t)(qBase + r) * IN_F + c4 * 4) * 2;
            *(uint2*)(g_Ah + base) = ph;
            *(uint2*)(g_Al + base) = pl;
        }
    }
    __threadfence();
    __syncthreads();
    if (tid == 0) {
        atomicAdd(&g_aDone[yb], 1);
        // wait for all 8 eighths of this m-tile
        while (ld_acquire(&g_aDone[yb]) < 8) __nanosleep(100);
        int old = atomicAdd(&g_aPassed[yb], 1);
        if (old == 7) { g_aDone[yb] = 0; g_aPassed[yb] = 0; }  // replay reset
    }
    __syncthreads();

    // ======== Phase 2: GEMM ========
    // A cp.async: 2 chunks/thread/tile; B: 1 chunk/thread/tile.
    const int r0 = tid >> 2, c0 = tid & 3;
    const int r1 = r0 + 64;
    const uint32_t offT0 = tile_off(r0, c0), offT1 = tile_off(r1, c0);

    const unsigned char* gAh0 = g_Ah + (size_t)(mBase + r0) * (IN_F * 2);
    const unsigned char* gAh1 = g_Ah + (size_t)(mBase + r1) * (IN_F * 2);
    const unsigned char* gAl0 = g_Al + (size_t)(mBase + r0) * (IN_F * 2);
    const unsigned char* gAl1 = g_Al + (size_t)(mBase + r1) * (IN_F * 2);
    const unsigned char* gBh0 = g_Bh + (size_t)(nBase + r0) * (IN_F * 2);
    const unsigned char* gBl0 = g_Bl + (size_t)(nBase + r0) * (IN_F * 2);

    auto load_stage = [&](int stg, int kt) {
        const uint32_t kb = (uint32_t)kt * 64 + c0 * 16;
        const uint32_t bs = sb + stg * STG_SZ;
        cp_async16(bs + offT0,          gAh0 + kb);
        cp_async16(bs + offT1,          gAh1 + kb);
        cp_async16(bs + 8192 + offT0,   gAl0 + kb);
        cp_async16(bs + 8192 + offT1,   gAl1 + kb);
        cp_async16(bs + 16384 + offT0,  gBh0 + kb);
        cp_async16(bs + 20480 + offT0,  gBl0 + kb);
    };

    float acc[2][4][4];
    #pragma unroll
    for (int mf = 0; mf < 2; mf++)
        #pragma unroll
        for (int nf = 0; nf < 4; nf++)
            #pragma unroll
            for (int d = 0; d < 4; d++) acc[mf][nf][d] = 0.0f;

    const int lrow = (lane & 7) + 8 * ((lane >> 3) & 1);
    const int lkc  = lane >> 4;

    // Precomputed swizzled offsets (ks==0, c=lkc). ks==1 addresses are ^32.
    uint32_t aoA[2], aoB[2];
    #pragma unroll
    for (int mf = 0; mf < 2; mf++)
        aoA[mf] = tile_off(wm * 32 + mf * 16 + lrow, lkc);
    #pragma unroll
    for (int g = 0; g < 2; g++)
        aoB[g] = tile_off(wn * 32 + g * 16 + lrow, lkc);

    load_stage(0, 0); CP_COMMIT();
    load_stage(1, 1); CP_COMMIT();

    for (int kt = 0; kt < NKT; kt++) {
        CP_WAIT1();
        __syncthreads();    // stage-kt complete; also orders stage reuse
        if (kt + 2 < NKT) load_stage((kt + 2) % 3, kt + 2);
        CP_COMMIT();

        const uint32_t bs = sb + (kt % 3) * STG_SZ;
        #pragma unroll
        for (int ks = 0; ks < 2; ks++) {
            const uint32_t xo = ks ? 32u : 0u;
            uint32_t ah[2][4], al[2][4], bh[2][4], bl[2][4];
            #pragma unroll
            for (int mf = 0; mf < 2; mf++) {
                ldmatrix_x4(ah[mf], bs + (aoA[mf] ^ xo));
                ldmatrix_x4(al[mf], bs + 8192 + (aoA[mf] ^ xo));
            }
            #pragma unroll
            for (int g = 0; g < 2; g++) {
                ldmatrix_x4(bh[g], bs + 16384 + (aoB[g] ^ xo));
                ldmatrix_x4(bl[g], bs + 20480 + (aoB[g] ^ xo));
            }
            #pragma unroll
            for (int g = 0; g < 2; g++) {
                float* a00 = acc[0][2 * g];
                float* a10 = acc[1][2 * g];
                float* a01 = acc[0][2 * g + 1];
                float* a11 = acc[1][2 * g + 1];
                // term 1: ah * bh
                mma16816(a00, ah[0], bh[g][0], bh[g][2]);
                mma16816(a10, ah[1], bh[g][0], bh[g][2]);
                mma16816(a01, ah[0], bh[g][1], bh[g][3]);
                mma16816(a11, ah[1], bh[g][1], bh[g][3]);
                // term 2: ah * bl
                mma16816(a00, ah[0], bl[g][0], bl[g][2]);
                mma16816(a10, ah[1], bl[g][0], bl[g][2]);
                mma16816(a01, ah[0], bl[g][1], bl[g][3]);
                mma16816(a11, ah[1], bl[g][1], bl[g][3]);
                // term 3: al * bh
                mma16816(a00, al[0], bh[g][0], bh[g][2]);
                mma16816(a10, al[1], bh[g][0], bh[g][2]);
                mma16816(a01, al[0], bh[g][1], bh[g][3]);
                mma16816(a11, al[1], bh[g][1], bh[g][3]);
            }
        }
        // no trailing barrier: next iteration's top sync provides the
        // stage-reuse ordering before any smem rewrite.
    }

    // ======== Phase 3: write I tile ========
    #pragma unroll
    for (int mf = 0; mf < 2; mf++) {
        #pragma unroll
        for (int nf = 0; nf < 4; nf++) {
            const int row = mBase + wm * 32 + mf * 16 + (lane >> 2);
            const int col = nBase + wn * 32 + nf * 8 + (lane & 3) * 2;
            float* p0 = g_I + (size_t)row * OUT_C + col;
            float* p1 = p0 + 8 * OUT_C;
            *(float2*)p0 = make_float2(acc[mf][nf][0], acc[mf][nf][1]);
            *(float2*)p1 = make_float2(acc[mf][nf][2], acc[mf][nf][3]);
        }
    }

    // ======== Phase 4: pairwise fused scan ========
    // Pair = tiles (y=2b, y=2b+1) at this nt. Second CTA to finish runs the
    // scan for batch b over its 64 columns (I is L2-hot).
    __threadfence();
    __shared__ int s_old;
    __syncthreads();
    const int b = yb >> 1;
    if (tid == 0) s_old = atomicAdd(&g_pDone[b * 8 + nt], 1);
    __syncthreads();

    if (s_old == 1) {
        __threadfence();   // acquire side: sibling's I writes are L2-visible
        if (tid < 64) {
            const int c = nBase + tid;
            const float* Ip = g_I + ((size_t)b * T_STEPS) * OUT_C + c;

            float V = 0.0f, refr = 0.0f, sc = 0.0f;
            int mode = 0;
            for (int t0 = 0; t0 < T_STEPS; t0 += 16) {
                float buf[16];
                #pragma unroll
                for (int j = 0; j < 16; j++)
                    buf[j] = Ip[(size_t)(t0 + j) * OUT_C];
                #pragma unroll
                for (int j = 0; j < 16; j++) {
                    const float I = buf[j];
                    const float v_std = fmaxf(V + I - LEAK, 0.0f);
                    const bool  fire  = (mode == 0) && (v_std > V_TH);
                    const float r_abs = fmaxf(refr - 1.0f, 0.0f);
                    const bool  done  = (r_abs <= 0.0f);
                    const float v_abs = fmaxf(V, 0.0f);
                    const float v_rel = fmaxf(V + REFR_LEAK, 0.0f);
                    const bool  back  = (v_rel > 0.0f);

                    const float Vn = (mode == 0) ? (fire ? 0.0f : v_std)
                                   : (mode == 1) ? v_abs : v_rel;
                    const float rn = (mode == 0) ? (fire ? REFRAC : refr)
                                   : (mode == 1) ? r_abs : refr;
                    const int   mn = (mode == 0) ? (fire ? 1 : 0)
                                   : (mode == 1) ? (done ? 2 : 1)
                                   : (back ? 0 : 2);
                    sc += fire ? 1.0f : 0.0f;
                    V = Vn; refr = rn; mode = mn;
                }
            }
            out[b * OUT_C + c] = sc;
        }
        __syncthreads();
        if (tid == 0) g_pDone[b * 8 + nt] = 0;   // replay reset
    }
}

// ---------------------------------------------------------------------------
extern "C" void kernel_launch(void* const* d_in, const int* in_sizes, int n_in,
                              void* d_out, int out_size) {
    const float* x_seq = (const float*)d_in[0];  // [B, T, F]
    const float* W     = (const float*)d_in[1];  // [F, C]
    float* out = (float*)d_out;                  // [B, C]

    cudaFuncSetAttribute(snn_fused,
                         cudaFuncAttributeMaxDynamicSharedMemorySize, GEMM_SMEM);

    conv_B_kernel<<<(IN_F * OUT_C) / 256, 256>>>(W);

    dim3 grid(OUT_C / 64, M_TOTAL / 128);        // (8, 256)
    snn_fused<<<grid, 256, GEMM_SMEM>>>(x_seq, out);
}

// round 13
// speedup vs baseline: 1.1460x; 1.1460x over previous
#include <cuda_runtime.h>
#include <cuda_bf16.h>
#include <cstdint>

// ---------------------------------------------------------------------------
// Problem constants
// ---------------------------------------------------------------------------
#define BATCH   128
#define T_STEPS 256
#define IN_F    1024
#define OUT_C   512
#define M_TOTAL (BATCH * T_STEPS)   // 32768
#define NKT     32                  // IN_F / 32 k-chunks

// SNN hyperparameters
#define V_TH      0.4f
#define LEAK      0.01f
#define REFR_LEAK 0.01f
#define REFRAC    2.0f

// ---------------------------------------------------------------------------
// Device scratch (static __device__: allocation-guard safe)
// ---------------------------------------------------------------------------
__device__ __align__(128) unsigned char g_Ah[(size_t)M_TOTAL * IN_F * 2]; // 64MB
__device__ __align__(128) unsigned char g_Al[(size_t)M_TOTAL * IN_F * 2]; // 64MB
__device__ __align__(128) unsigned char g_Bh[(size_t)OUT_C * IN_F * 2];   // 1MB
__device__ __align__(128) unsigned char g_Bl[(size_t)OUT_C * IN_F * 2];   // 1MB
__device__ float g_I[(size_t)M_TOTAL * OUT_C];                            // 64MB

// Cross-CTA dataflow flags (zero-init; protocols restore 0 every run).
__device__ int g_aDone[256];     // quarters converted per m-tile (0..4)
__device__ int g_aPassed[256];   // consumers past the spin     (0..4)
__device__ int g_pDone[128 * 4]; // I-tiles written per (b, nt) pair (0..2)

// ---------------------------------------------------------------------------
// Helpers (base sm_80/90 ISA only — nothing 'a'-gated)
// ---------------------------------------------------------------------------
__device__ __forceinline__ uint32_t smem_u32(const void* p) {
    uint32_t a;
    asm("{ .reg .u64 t; cvta.to.shared.u64 t, %1; cvt.u32.u64 %0, t; }"
        : "=r"(a) : "l"(p));
    return a;
}

__device__ __forceinline__ void cp_async16(uint32_t dst, const void* src) {
    asm volatile("cp.async.cg.shared.global [%0], [%1], 16;"
                 :: "r"(dst), "l"(src) : "memory");
}

#define MBAR_INIT(addr, cnt) \
    asm volatile("mbarrier.init.shared.b64 [%0], %1;" \
        :: "r"((uint32_t)(addr)), "r"((uint32_t)(cnt)) : "memory")

#define MBAR_ARRIVE(addr) \
    asm volatile("mbarrier.arrive.shared.b64 _, [%0];" \
        :: "r"((uint32_t)(addr)) : "memory")

// Signal [addr] (without incrementing expected count) once all of THIS
// thread's previously-issued cp.async ops have completed.
#define CP_MBAR_ARRIVE(addr) \
    asm volatile("cp.async.mbarrier.arrive.noinc.shared.b64 [%0];" \
        :: "r"((uint32_t)(addr)) : "memory")

#define MBAR_WAIT(mbar_smem_addr, phase_parity) do { \
    uint32_t _mbar = (uint32_t)(mbar_smem_addr); \
    uint32_t _parity = (uint32_t)(phase_parity); \
    uint32_t _done; \
    asm volatile( \
        "{\n\t.reg .pred p;\n\t" \
        "mbarrier.try_wait.parity.acquire.cta.shared::cta.b64 p, [%1], %2;\n\t" \
        "selp.b32 %0, 1, 0, p;\n\t}" \
        : "=r"(_done) : "r"(_mbar), "r"(_parity) : "memory"); \
    if (!_done) { \
        asm volatile( \
            "{\n\t.reg .pred P1;\n\t" \
            "WAIT_LOOP_%=:\n\t" \
            "mbarrier.try_wait.parity.acquire.cta.shared::cta.b64 P1, [%0], %1, 0x989680;\n\t" \
            "@P1 bra.uni WAIT_DONE_%=;\n\t" \
            "bra.uni WAIT_LOOP_%=;\n\t" \
            "WAIT_DONE_%=:\n\t}" \
            :: "r"(_mbar), "r"(_parity) : "memory"); \
    } \
} while (0)

__device__ __forceinline__ void ldmatrix_x4(uint32_t* r, uint32_t addr) {
    asm volatile("ldmatrix.sync.aligned.m8n8.x4.shared.b16 {%0,%1,%2,%3}, [%4];"
                 : "=r"(r[0]), "=r"(r[1]), "=r"(r[2]), "=r"(r[3]) : "r"(addr));
}

__device__ __forceinline__ void mma16816(float* d, const uint32_t* a,
                                         uint32_t b0, uint32_t b1) {
    asm volatile(
        "mma.sync.aligned.m16n8k16.row.col.f32.bf16.bf16.f32 "
        "{%0,%1,%2,%3}, {%4,%5,%6,%7}, {%8,%9}, {%0,%1,%2,%3};"
        : "+f"(d[0]), "+f"(d[1]), "+f"(d[2]), "+f"(d[3])
        : "r"(a[0]), "r"(a[1]), "r"(a[2]), "r"(a[3]), "r"(b0), "r"(b1));
}

__device__ __forceinline__ int ld_acquire(const int* p) {
    int v;
    asm volatile("ld.acquire.gpu.s32 %0, [%1];" : "=r"(v) : "l"(p) : "memory");
    return v;
}

// Swizzled byte offset within a 128-row x 64-byte tile (conflict-free ldmatrix).
// Packs 2 rows per 128B line. Property: tile_off(r, c+2) == tile_off(r, c) ^ 32.
__device__ __forceinline__ uint32_t tile_off(int r, int c) {
    int line = r >> 1;
    int ch8 = (((r & 1) * 4 + c) ^ (line & 7));
    return (uint32_t)(line * 128 + ch8 * 16);
}

// fp32 -> (hi, lo) bf16 pair packers
__device__ __forceinline__ void split4(float4 v, uint2& ph, uint2& pl) {
    __nv_bfloat16 h0 = __float2bfloat16_rn(v.x);
    __nv_bfloat16 h1 = __float2bfloat16_rn(v.y);
    __nv_bfloat16 h2 = __float2bfloat16_rn(v.z);
    __nv_bfloat16 h3 = __float2bfloat16_rn(v.w);
    __nv_bfloat16 l0 = __float2bfloat16_rn(v.x - __bfloat162float(h0));
    __nv_bfloat16 l1 = __float2bfloat16_rn(v.y - __bfloat162float(h1));
    __nv_bfloat16 l2 = __float2bfloat16_rn(v.z - __bfloat162float(h2));
    __nv_bfloat16 l3 = __float2bfloat16_rn(v.w - __bfloat162float(h3));
    ph.x = ((uint32_t)__bfloat16_as_ushort(h1) << 16) | __bfloat16_as_ushort(h0);
    ph.y = ((uint32_t)__bfloat16_as_ushort(h3) << 16) | __bfloat16_as_ushort(h2);
    pl.x = ((uint32_t)__bfloat16_as_ushort(l1) << 16) | __bfloat16_as_ushort(l0);
    pl.y = ((uint32_t)__bfloat16_as_ushort(l3) << 16) | __bfloat16_as_ushort(l2);
}

// ---------------------------------------------------------------------------
// conv_B: W fp32 [1024 k][512 n] -> g_Bh / g_Bl bf16 [n][1024 k]
// ---------------------------------------------------------------------------
__global__ __launch_bounds__(256)
void conv_B_kernel(const float* __restrict__ W) {
    const uint32_t i = blockIdx.x * 256 + threadIdx.x;   // 0 .. 524287
    const uint32_t k = i & 1023;
    const uint32_t n = i >> 10;
    float w = W[(size_t)k * OUT_C + n];
    __nv_bfloat16 hi = __float2bfloat16_rn(w);
    __nv_bfloat16 lo = __float2bfloat16_rn(w - __bfloat162float(hi));
    *(unsigned short*)(g_Bh + ((size_t)n * IN_F + k) * 2) = __bfloat16_as_ushort(hi);
    *(unsigned short*)(g_Bl + ((size_t)n * IN_F + k) * 2) = __bfloat16_as_ushort(lo);
}

// ---------------------------------------------------------------------------
// Fused kernel (R8 geometry): A-convert (quarter/CTA) -> GEMM -> I -> scan.
// CTA 128x128, BK=32, 8 warps (4x2, warp tile 32x64), mma.sync 16x8x16.
// NEW: mbarrier-phased 3-stage pipeline (full/empty per stage) instead of
// cp.async.wait_group + __syncthreads — warps skew freely within the window,
// so one warp's stall no longer blocks the other seven.
// ---------------------------------------------------------------------------
#define STG_SZ  32768
#define SM_HDR  1024
#define GEMM_SMEM (SM_HDR + 3 * STG_SZ)   // 97KB -> 2 CTAs/SM

__global__ __launch_bounds__(256, 2)
void snn_fused(const float* __restrict__ x, float* __restrict__ out) {
    extern __shared__ __align__(1024) unsigned char dsm[];
    const uint32_t sb = smem_u32(dsm);
    const uint32_t FULL  = sb;        // 3 x 8B
    const uint32_t EMPTY = sb + 24;   // 3 x 8B
    const uint32_t STG0  = sb + SM_HDR;

    const int tid  = threadIdx.x;
    const int lane = tid & 31;
    const int wid  = tid >> 5;
    const int wm   = wid >> 1;          // 0..3
    const int wn   = wid & 1;           // 0..1
    const int nt   = blockIdx.x;        // 0..3
    const int yb   = blockIdx.y;        // 0..255
    const int mBase = yb * 128;
    const int nBase = nt * 128;

    // mbarrier init (before any pipeline use)
    if (tid == 0) {
        #pragma unroll
        for (int s = 0; s < 3; s++) {
            MBAR_INIT(FULL + s * 8, 256);
            MBAR_INIT(EMPTY + s * 8, 256);
        }
    }
    __syncthreads();

    // ======== Phase 1: convert this CTA's quarter (32 rows) of A ========
    {
        const int qBase = mBase + nt * 32;
        const float4* src = (const float4*)x + (size_t)qBase * 256;
        #pragma unroll 4
        for (int it = 0; it < 32; it++) {
            const int idx = it * 256 + tid;          // 0..8191
            const int r   = idx >> 8;                // 0..31
            const int c4  = idx & 255;
            uint2 ph, pl;
            split4(src[(size_t)r * 256 + c4], ph, pl);
            const size_t base = ((size_t)(qBase + r) * IN_F + c4 * 4) * 2;
            *(uint2*)(g_Ah + base) = ph;
            *(uint2*)(g_Al + base) = pl;
        }
    }
    __threadfence();
    __syncthreads();
    if (tid == 0) {
        atomicAdd(&g_aDone[yb], 1);
        while (ld_acquire(&g_aDone[yb]) < 4) __nanosleep(100);
        int old = atomicAdd(&g_aPassed[yb], 1);
        if (old == 3) { g_aDone[yb] = 0; g_aPassed[yb] = 0; }  // replay reset
    }
    __syncthreads();

    // ======== Phase 2: GEMM with mbarrier-phased pipeline ========
    const int r0 = tid >> 2, c0 = tid & 3;
    const int r1 = r0 + 64;
    const uint32_t offT0 = tile_off(r0, c0), offT1 = tile_off(r1, c0);

    const unsigned char* gAh0 = g_Ah + (size_t)(mBase + r0) * (IN_F * 2);
    const unsigned char* gAh1 = g_Ah + (size_t)(mBase + r1) * (IN_F * 2);
    const unsigned char* gAl0 = g_Al + (size_t)(mBase + r0) * (IN_F * 2);
    const unsigned char* gAl1 = g_Al + (size_t)(mBase + r1) * (IN_F * 2);
    const unsigned char* gBh0 = g_Bh + (size_t)(nBase + r0) * (IN_F * 2);
    const unsigned char* gBh1 = g_Bh + (size_t)(nBase + r1) * (IN_F * 2);
    const unsigned char* gBl0 = g_Bl + (size_t)(nBase + r0) * (IN_F * 2);
    const unsigned char* gBl1 = g_Bl + (size_t)(nBase + r1) * (IN_F * 2);

    // Issue this thread's 8 cp.async chunks for stage (fkt%3) of k-chunk fkt,
    // then bind completion to the stage's FULL mbarrier.
    auto fill_stage = [&](int fkt) {
        const int fs = fkt % 3;
        const uint32_t kb = (uint32_t)fkt * 64 + c0 * 16;
        const uint32_t bs = STG0 + fs * STG_SZ;
        cp_async16(bs + offT0,          gAh0 + kb);
        cp_async16(bs + offT1,          gAh1 + kb);
        cp_async16(bs + 8192 + offT0,   gAl0 + kb);
        cp_async16(bs + 8192 + offT1,   gAl1 + kb);
        cp_async16(bs + 16384 + offT0,  gBh0 + kb);
        cp_async16(bs + 16384 + offT1,  gBh1 + kb);
        cp_async16(bs + 24576 + offT0,  gBl0 + kb);
        cp_async16(bs + 24576 + offT1,  gBl1 + kb);
        CP_MBAR_ARRIVE(FULL + fs * 8);
    };

    float acc[2][8][4];
    #pragma unroll
    for (int mf = 0; mf < 2; mf++)
        #pragma unroll
        for (int nf = 0; nf < 8; nf++)
            #pragma unroll
            for (int d = 0; d < 4; d++) acc[mf][nf][d] = 0.0f;

    const int lrow = (lane & 7) + 8 * ((lane >> 3) & 1);
    const int lkc  = lane >> 4;

    // Precomputed swizzled offsets (ks==0, c=lkc). ks==1 addresses are ^32.
    uint32_t aoA[2], aoB[4];
    #pragma unroll
    for (int mf = 0; mf < 2; mf++)
        aoA[mf] = tile_off(wm * 32 + mf * 16 + lrow, lkc);
    #pragma unroll
    for (int g = 0; g < 4; g++)
        aoB[g] = tile_off(wn * 64 + g * 16 + lrow, lkc);

    // prologue fills (fill #0 of stages 0 and 1 — no empty wait needed)
    fill_stage(0);
    fill_stage(1);

    for (int kt = 0; kt < NKT; kt++) {
        const int s = kt % 3;
        // consume: wait until ALL 256 threads' copies for k-chunk kt landed
        MBAR_WAIT(FULL + s * 8, (kt / 3) & 1);

        const uint32_t bs = STG0 + s * STG_SZ;
        #pragma unroll
        for (int ks = 0; ks < 2; ks++) {
            const uint32_t xo = ks ? 32u : 0u;
            uint32_t ah[2][4], al[2][4];
            #pragma unroll
            for (int mf = 0; mf < 2; mf++) {
                ldmatrix_x4(ah[mf], bs + (aoA[mf] ^ xo));
                ldmatrix_x4(al[mf], bs + 8192 + (aoA[mf] ^ xo));
            }
            uint32_t bh[2][4], bl[2][4];
            ldmatrix_x4(bh[0], bs + 16384 + (aoB[0] ^ xo));
            ldmatrix_x4(bl[0], bs + 24576 + (aoB[0] ^ xo));
            #pragma unroll
            for (int g = 0; g < 4; g++) {
                const int cur = g & 1, nxt = cur ^ 1;
                if (g < 3) {
                    ldmatrix_x4(bh[nxt], bs + 16384 + (aoB[g + 1] ^ xo));
                    ldmatrix_x4(bl[nxt], bs + 24576 + (aoB[g + 1] ^ xo));
                }
                float* a00 = acc[0][2 * g];
                float* a10 = acc[1][2 * g];
                float* a01 = acc[0][2 * g + 1];
                float* a11 = acc[1][2 * g + 1];
                // term 1: ah * bh
                mma16816(a00, ah[0], bh[cur][0], bh[cur][2]);
                mma16816(a10, ah[1], bh[cur][0], bh[cur][2]);
                mma16816(a01, ah[0], bh[cur][1], bh[cur][3]);
                mma16816(a11, ah[1], bh[cur][1], bh[cur][3]);
                // term 2: ah * bl
                mma16816(a00, ah[0], bl[cur][0], bl[cur][2]);
                mma16816(a10, ah[1], bl[cur][0], bl[cur][2]);
                mma16816(a01, ah[0], bl[cur][1], bl[cur][3]);
                mma16816(a11, ah[1], bl[cur][1], bl[cur][3]);
                // term 3: al * bh
                mma16816(a00, al[0], bh[cur][0], bh[cur][2]);
                mma16816(a10, al[1], bh[cur][0], bh[cur][2]);
                mma16816(a01, al[0], bh[cur][1], bh[cur][3]);
                mma16816(a11, al[1], bh[cur][1], bh[cur][3]);
            }
        }

        // done reading stage s for this thread
        MBAR_ARRIVE(EMPTY + s * 8);

        // produce k-chunk kt+2 into its stage (fill #f needs consumption
        // #f-1 of that stage complete = EMPTY flip #(f-1))
        const int fkt = kt + 2;
        if (fkt < NKT) {
            const int f = fkt / 3;
            if (f >= 1) MBAR_WAIT(EMPTY + (fkt % 3) * 8, (f - 1) & 1);
            fill_stage(fkt);
        }
    }

    // ======== Phase 3: write I tile ========
    #pragma unroll
    for (int mf = 0; mf < 2; mf++) {
        #pragma unroll
        for (int nf = 0; nf < 8; nf++) {
            const int row = mBase + wm * 32 + mf * 16 + (lane >> 2);
            const int col = nBase + wn * 64 + nf * 8 + (lane & 3) * 2;
            float* p0 = g_I + (size_t)row * OUT_C + col;
            float* p1 = p0 + 8 * OUT_C;
            *(float2*)p0 = make_float2(acc[mf][nf][0], acc[mf][nf][1]);
            *(float2*)p1 = make_float2(acc[mf][nf][2], acc[mf][nf][3]);
        }
    }

    // ======== Phase 4: pairwise fused scan ========
    __threadfence();
    __shared__ int s_old;
    __syncthreads();
    const int b = yb >> 1;
    if (tid == 0) s_old = atomicAdd(&g_pDone[b * 4 + nt], 1);
    __syncthreads();

    if (s_old == 1) {
        __threadfence();   // acquire side: sibling's I writes are L2-visible
        if (tid < 128) {
            const int c = nBase + tid;
            const float* Ip = g_I + ((size_t)b * T_STEPS) * OUT_C + c;

            float V = 0.0f, refr = 0.0f, sc = 0.0f;
            int mode = 0;
            for (int t0 = 0; t0 < T_STEPS; t0 += 16) {
                float buf[16];
                #pragma unroll
                for (int j = 0; j < 16; j++)
                    buf[j] = Ip[(size_t)(t0 + j) * OUT_C];
                #pragma unroll
                for (int j = 0; j < 16; j++) {
                    const float I = buf[j];
                    const float v_std = fmaxf(V + I - LEAK, 0.0f);
                    const bool  fire  = (mode == 0) && (v_std > V_TH);
                    const float r_abs = fmaxf(refr - 1.0f, 0.0f);
                    const bool  done  = (r_abs <= 0.0f);
                    const float v_abs = fmaxf(V, 0.0f);
                    const float v_rel = fmaxf(V + REFR_LEAK, 0.0f);
                    const bool  back  = (v_rel > 0.0f);

                    const float Vn = (mode == 0) ? (fire ? 0.0f : v_std)
                                   : (mode == 1) ? v_abs : v_rel;
                    const float rn = (mode == 0) ? (fire ? REFRAC : refr)
                                   : (mode == 1) ? r_abs : refr;
                    const int   mn = (mode == 0) ? (fire ? 1 : 0)
                                   : (mode == 1) ? (done ? 2 : 1)
                                   : (back ? 0 : 2);
                    sc += fire ? 1.0f : 0.0f;
                    V = Vn; refr = rn; mode = mn;
                }
            }
            out[b * OUT_C + c] = sc;
        }
        __syncthreads();
        if (tid == 0) g_pDone[b * 4 + nt] = 0;   // replay reset
    }
}

// ---------------------------------------------------------------------------
extern "C" void kernel_launch(void* const* d_in, const int* in_sizes, int n_in,
                              void* d_out, int out_size) {
    const float* x_seq = (const float*)d_in[0];  // [B, T, F]
    const float* W     = (const float*)d_in[1];  // [F, C]
    float* out = (float*)d_out;                  // [B, C]

    cudaFuncSetAttribute(snn_fused,
                         cudaFuncAttributeMaxDynamicSharedMemorySize, GEMM_SMEM);

    conv_B_kernel<<<(IN_F * OUT_C) / 256, 256>>>(W);

    dim3 grid(OUT_C / 128, M_TOTAL / 128);       // (4, 256)
    snn_fused<<<grid, 256, GEMM_SMEM>>>(x_seq, out);
}